// round 7
// baseline (speedup 1.0000x reference)
#include <cuda_runtime.h>
#include <math.h>

#define Bn    128
#define Tn    128
#define In    512
#define Hn    512
#define Dn    1024
#define Nn    513
#define NP    576          // padded col stride (9 strips of 64)
#define DEPTH 4
#define EPSV  1e-5f
#define NCTA  148
#define GCTA  74           // CTAs per group
#define GB    64           // batches per group
#define NTHR  256

// ----------------------------- device state --------------------------------
__device__ float g_Wp[Dn * NP];
__device__ float g_Up[Dn * NP];
__device__ float g_X[Tn * Bn * Dn];        // xs / h_seq in place, row = t*Bn+b
__device__ float g_XWraw[Tn * Bn * NP];
__device__ float g_spre[Tn * Bn * NP];
__device__ float g_Gpart[16 * GB * NP];    // [group*8+ks][64 rows][NP]
__device__ float g_h[Bn * Dn];
__device__ float g_fk[Bn];
__device__ float g_hv[Bn];
__device__ float g_fkseq[Tn * Bn];
__device__ float g_hvseq[Tn * Bn];
__device__ unsigned g_barCnt[4];           // 0,1: groups; 2: global
__device__ unsigned g_barEp[4];

// ------------------------------ barriers ------------------------------------
__device__ __forceinline__ void barrier_sync(int idx, int n, unsigned& ep) {
    __syncthreads();
    if (threadIdx.x == 0) {
        ep += 1;
        __threadfence();
        unsigned prev = atomicAdd(&g_barCnt[idx], 1u);
        if (prev == (unsigned)(n - 1)) {
            atomicExch(&g_barCnt[idx], 0u);
            __threadfence();
            atomicExch(&g_barEp[idx], ep);
        } else {
            while (atomicAdd(&g_barEp[idx], 0u) < ep) { }
        }
        __threadfence();
    }
    __syncthreads();
}

// --------------------- 64x64 tile GEMM (C-strides = NP) ---------------------
// A: 64 rows, stride lda; B: K x 64 at Bm, stride NP; C: 64 x 64, stride NP.
// 256 threads, 4x4 microtile, K multiple of 16, software-pipelined LDG.
__device__ __forceinline__ void tile_gemm64(
    const float* __restrict__ A, int lda,
    const float* __restrict__ Bm,
    float* __restrict__ C, int K, float* sh)
{
    float* hT = sh;            // [16][68]
    float* Us = sh + 16 * 68;  // [16][64]
    int tid  = threadIdx.x;
    int arow = tid >> 2, akq = (tid & 3) << 2;
    int brow = tid >> 4, bc  = (tid & 15) << 2;
    int ty   = tid >> 4, tx  = tid & 15;

    float acc[4][4];
#pragma unroll
    for (int i = 0; i < 4; i++)
#pragma unroll
        for (int j = 0; j < 4; j++) acc[i][j] = 0.f;

    const float* Aptr = A + arow * lda + akq;
    const float* Bptr = Bm + brow * NP + bc;
    float4 av = *(const float4*)Aptr;
    float4 bv = *(const float4*)Bptr;

    for (int k0 = 0; k0 < K; k0 += 16) {
        __syncthreads();
        hT[(akq + 0) * 68 + arow] = av.x;
        hT[(akq + 1) * 68 + arow] = av.y;
        hT[(akq + 2) * 68 + arow] = av.z;
        hT[(akq + 3) * 68 + arow] = av.w;
        *(float4*)(Us + (brow << 6) + bc) = bv;
        __syncthreads();
        if (k0 + 16 < K) {
            av = *(const float4*)(Aptr + k0 + 16);
            bv = *(const float4*)(Bptr + (size_t)(k0 + 16) * NP);
        }
#pragma unroll
        for (int kk = 0; kk < 16; kk++) {
            float4 a  = *(float4*)(hT + kk * 68 + (ty << 2));
            float4 b4 = *(float4*)(Us + (kk << 6) + (tx << 2));
            acc[0][0] += a.x * b4.x; acc[0][1] += a.x * b4.y;
            acc[0][2] += a.x * b4.z; acc[0][3] += a.x * b4.w;
            acc[1][0] += a.y * b4.x; acc[1][1] += a.y * b4.y;
            acc[1][2] += a.y * b4.z; acc[1][3] += a.y * b4.w;
            acc[2][0] += a.z * b4.x; acc[2][1] += a.z * b4.y;
            acc[2][2] += a.z * b4.z; acc[2][3] += a.z * b4.w;
            acc[3][0] += a.w * b4.x; acc[3][1] += a.w * b4.y;
            acc[3][2] += a.w * b4.z; acc[3][3] += a.w * b4.w;
        }
    }
#pragma unroll
    for (int i = 0; i < 4; i++) {
        *(float4*)(C + (size_t)((ty << 2) + i) * NP + (tx << 2)) =
            make_float4(acc[i][0], acc[i][1], acc[i][2], acc[i][3]);
    }
}

// ------------------------------ main kernel ---------------------------------
__global__ void __launch_bounds__(NTHR, 1) hrnn_kernel(
    const float* __restrict__ x, const int* __restrict__ mask,
    const float* __restrict__ W, const float* __restrict__ U,
    const float* __restrict__ bias, const float* __restrict__ gam,
    const float* __restrict__ bet, float* __restrict__ out)
{
    __shared__ float sh_gemm[16 * 68 + 16 * 64];
    __shared__ float sh_s[Nn];
    __shared__ float sh_red[16];
    __shared__ float sh_sc[8];

    int cta = blockIdx.x, tid = threadIdx.x;
    int gtid = cta * NTHR + tid;
    const int nthr = NCTA * NTHR;

    // ------------------------------- prep -----------------------------------
    for (int i = gtid; i < Tn * Bn * Dn; i += nthr) {
        int d = i & (Dn - 1);
        int row = i >> 10;
        int t = row >> 7, b = row & 127;
        g_X[i] = (d < In) ? x[(b * Tn + t) * In + d] : 0.f;
    }
    for (int i = gtid; i < Dn * NP; i += nthr) {
        int col = i % NP, r = i / NP;
        float wv = 0.f, uv = 0.f;
        if (col < Nn) { wv = W[r * Nn + col]; uv = U[r * Nn + col]; }
        g_Wp[i] = wv;
        g_Up[i] = uv;
    }
    for (int i = gtid; i < Tn * Bn; i += nthr) { g_fkseq[i] = 0.f; g_hvseq[i] = 1.f; }

    int g = cta / GCTA;      // group 0/1
    int c = cta % GCTA;      // CTA within group
    unsigned epG = 0, epL = 0;
    if (tid == 0) {
        epG = atomicAdd(&g_barEp[2], 0u);   // persistent-counter-safe base
        epL = atomicAdd(&g_barEp[g], 0u);
    }
    barrier_sync(2, NCTA, epG);

    const float* gam0 = gam;
    const float* gam1 = gam + Nn;
    const float* bet0 = bet;
    const float* bet1 = bet + Nn;
    const int b0g = g * GB;

    for (int lev = 0; lev < DEPTH; lev++) {
        // ---------------- xW GEMM: 128 t-tiles x 9 col strips ----------------
        for (int tau = c; tau < Tn * 9; tau += GCTA) {
            int t = tau / 9, j = tau - t * 9;
            tile_gemm64(&g_X[(size_t)(t * Bn + b0g) * Dn], Dn,
                        &g_Wp[j * 64],
                        &g_XWraw[(size_t)(t * Bn + b0g) * NP + j * 64],
                        Dn, sh_gemm);
        }
        barrier_sync(g, GCTA, epL);

        // ---------------- LN of xW rows -> spre; init carries ----------------
        for (int lr = c; lr < Tn * GB; lr += GCTA) {
            int t = lr >> 6, bl = lr & 63;
            const float* row = &g_XWraw[(size_t)(t * Bn + b0g + bl) * NP];
            float v0 = row[tid];
            float v1 = row[tid + 256];
            float v2 = (tid == 0) ? row[512] : 0.f;
            float s = v0 + v1 + v2;
            float q = v0 * v0 + v1 * v1 + v2 * v2;
#pragma unroll
            for (int o = 16; o > 0; o >>= 1) {
                s += __shfl_down_sync(0xffffffffu, s, o);
                q += __shfl_down_sync(0xffffffffu, q, o);
            }
            if ((tid & 31) == 0) { sh_red[tid >> 5] = s; sh_red[8 + (tid >> 5)] = q; }
            __syncthreads();
            if (tid == 0) {
                float S = 0.f, Q = 0.f;
#pragma unroll
                for (int w = 0; w < 8; w++) { S += sh_red[w]; Q += sh_red[8 + w]; }
                float mean = S * (1.f / (float)Nn);
                float var  = Q * (1.f / (float)Nn) - mean * mean;
                sh_sc[0] = mean;
                sh_sc[1] = 1.f / (sqrtf(var + EPSV) + EPSV);
            }
            __syncthreads();
            float mean = sh_sc[0], inv = sh_sc[1];
            float* o = &g_spre[(size_t)(t * Bn + b0g + bl) * NP];
            o[tid]       = gam0[tid] * ((v0 - mean) * inv) + bet0[tid] + bias[tid];
            o[tid + 256] = gam0[tid + 256] * ((v1 - mean) * inv) + bet0[tid + 256] + bias[tid + 256];
            if (tid == 0)
                o[512] = gam0[512] * ((v2 - mean) * inv) + bet0[512] + bias[512];
            __syncthreads();
        }
        for (int i = c * NTHR + tid; i < GB * Dn; i += GCTA * NTHR)
            g_h[b0g * Dn + i] = 0.f;
        for (int i = c * NTHR + tid; i < GB; i += GCTA * NTHR) {
            g_fk[b0g + i] = 0.f;
            g_hv[b0g + i] = 0.f;
        }
        barrier_sync(g, GCTA, epL);

        // ------------------------------ scan ---------------------------------
        for (int t = 0; t < Tn; t++) {
            // phase A: split-K h@U partials
            if (c < 72) {
                int j = c >> 3, ks = c & 7;
                tile_gemm64(&g_h[(size_t)b0g * Dn + ks * 128], Dn,
                            &g_Up[(size_t)(ks * 128) * NP + j * 64],
                            &g_Gpart[(size_t)((g * 8 + ks) * GB) * NP + j * 64],
                            128, sh_gemm);
            }
            barrier_sync(g, GCTA, epL);

            // phase B: one CTA per batch
            if (c < GB) {
                int b = b0g + c;
                float v0 = 0.f, v1 = 0.f, v2 = 0.f;
#pragma unroll
                for (int ks = 0; ks < 8; ks++) {
                    const float* gp = &g_Gpart[(size_t)((g * 8 + ks) * GB + c) * NP];
                    v0 += gp[tid];
                    v1 += gp[tid + 256];
                    if (tid == 0) v2 += gp[512];
                }
                float s = v0 + v1 + v2;
                float q = v0 * v0 + v1 * v1 + v2 * v2;
#pragma unroll
                for (int o = 16; o > 0; o >>= 1) {
                    s += __shfl_down_sync(0xffffffffu, s, o);
                    q += __shfl_down_sync(0xffffffffu, q, o);
                }
                if ((tid & 31) == 0) { sh_red[tid >> 5] = s; sh_red[8 + (tid >> 5)] = q; }
                __syncthreads();
                if (tid == 0) {
                    float S = 0.f, Q = 0.f;
#pragma unroll
                    for (int w = 0; w < 8; w++) { S += sh_red[w]; Q += sh_red[8 + w]; }
                    float mean = S * (1.f / (float)Nn);
                    float var  = Q * (1.f / (float)Nn) - mean * mean;
                    sh_sc[0] = mean;
                    sh_sc[1] = 1.f / (sqrtf(var + EPSV) + EPSV);
                }
                __syncthreads();
                float mean = sh_sc[0], inv = sh_sc[1];

                const float* sp = &g_spre[(size_t)(t * Bn + b) * NP];
                float sum2_0 = gam1[0] * ((v0 - mean) * inv) + bet1[0]; // tid 0 only
                float s0 = sp[tid]       + gam1[tid]       * ((v0 - mean) * inv) + bet1[tid];
                float s1 = sp[tid + 256] + gam1[tid + 256] * ((v1 - mean) * inv) + bet1[tid + 256];
                sh_s[tid]       = s0;
                sh_s[tid + 256] = s1;
                if (tid == 0)
                    sh_s[512] = sp[512] + gam1[512] * ((v2 - mean) * inv) + bet1[512];

                if (tid == 0) {
                    float fk_tm1  = g_fk[b];
                    float hv_tm1  = g_hv[b];
                    float fkp_tm1 = g_fkseq[t * Bn + b];
                    float fkp     = (t + 1 < Tn) ? g_fkseq[(t + 1) * Bn + b] : 0.f;
                    float hvp     = g_hvseq[t * Bn + b];
                    bool  mk      = mask[b * Tn + t] > 0;
                    bool  mkprev  = (t > 0) ? (mask[b * Tn + t - 1] > 0) : false;
                    bool  mk2     = (t > 0) && mkprev && !mk;

                    float fk_both = fminf(fmaxf(0.2f * s0 + 0.5f, 0.f), 1.f);
                    float fk_t1   = fminf(fmaxf(0.2f * (sum2_0 + bias[0]) + 0.5f, 0.f), 1.f);
                    float fk = fkp_tm1 + (1.f - fkp_tm1) *
                               (fk_tm1 * fk_both + (1.f - fk_tm1) * fk_t1);
                    if (mk2) fk = 0.f;

                    float h_only = hv_tm1 * fk * (fkp + (1.f - fkp) * (1.f - hvp));
                    float x_only = hvp * (1.f - fkp) * (1.f - fk + fk * (1.f - hv_tm1));
                    float both   = (1.f - fkp) * fk * hv_tm1 * hvp;
                    float hv = 1.f - (1.f - h_only) * (1.f - x_only) * (1.f - both);

                    float fk_out = mk ? fk : fk_tm1;
                    float hv_out = mk ? hv : hv_tm1;
                    if (mk2) fk_out = 0.f;

                    sh_sc[2] = h_only; sh_sc[3] = x_only;
                    sh_sc[4] = both;   sh_sc[5] = mk ? 1.f : 0.f;

                    g_fk[b] = fk_out;
                    g_hv[b] = hv_out;
                    g_fkseq[t * Bn + b] = fk_out;
                    g_hvseq[t * Bn + b] = hv_out;
                }
                __syncthreads();

                float h_only = sh_sc[2], x_only = sh_sc[3];
                float both = sh_sc[4], mkf = sh_sc[5];
#pragma unroll
                for (int e = 0; e < 4; e++) {
                    int d = tid + (e << 8);
                    float x_t   = g_X[(size_t)(t * Bn + b) * Dn + d];
                    float h_tm1 = g_h[(size_t)b * Dn + d];
                    float h_new = (d < In) ? 0.f : tanhf(sh_s[d - (In - 1)]);
                    float h = h_only * h_tm1 + x_only * x_t + both * h_new;
                    h = mkf * h + (1.f - mkf) * h_tm1;
                    g_h[(size_t)b * Dn + d] = h;
                    g_X[(size_t)(t * Bn + b) * Dn + d] = h;
                }
            }
            barrier_sync(g, GCTA, epL);
        }
    }

    // ------------------------------ output ----------------------------------
    for (int i = c * NTHR + tid; i < GB * Hn; i += GCTA * NTHR) {
        int bl = i >> 9, j = i & 511;
        out[(size_t)(b0g + bl) * Hn + j] = g_h[(size_t)(b0g + bl) * Dn + In + j];
    }
}

// ------------------------------- launcher -----------------------------------
extern "C" void kernel_launch(void* const* d_in, const int* in_sizes, int n_in,
                              void* d_out, int out_size) {
    const float* x      = (const float*)d_in[0];
    const int*   mask   = (const int*)d_in[1];
    const float* W      = (const float*)d_in[2];
    const float* U      = (const float*)d_in[3];
    const float* bias   = (const float*)d_in[4];
    const float* gammas = (const float*)d_in[5];
    const float* betas  = (const float*)d_in[6];
    float* out = (float*)d_out;

    hrnn_kernel<<<NCTA, NTHR>>>(x, mask, W, U, bias, gammas, betas, out);
}

// round 8
// speedup vs baseline: 1.0155x; 1.0155x over previous
#include <cuda_runtime.h>
#include <math.h>

#define Bn    128
#define Tn    128
#define In    512
#define Hn    512
#define Dn    1024
#define Nn    513
#define NP    576          // padded col stride (9 strips of 64)
#define DEPTH 4
#define EPSV  1e-5f
#define NCTA  148
#define GCTA  74           // CTAs per group
#define GB    64           // batches per group
#define NTHR  256

typedef unsigned long long u64t;

// ----------------------------- device state --------------------------------
__device__ float g_Wp[Dn * NP];
__device__ float g_Up[Dn * NP];
__device__ float g_X[Tn * Bn * Dn];        // xs / h_seq in place, row = t*Bn+b
__device__ float g_XWraw[Tn * Bn * NP];
__device__ float g_spre[Tn * Bn * NP];
__device__ float g_Gpart[16 * GB * NP];    // [group*8+ks][64 rows][NP]
__device__ float g_h[Bn * Dn];
__device__ float g_fk[Bn];
__device__ float g_hv[Bn];
__device__ float g_fkseq[Tn * Bn];
__device__ float g_hvseq[Tn * Bn];
__device__ unsigned g_barCnt[4];           // 0,1: groups; 2: global
__device__ unsigned g_barEp[4];

// --------------------------- f32x2 packed math ------------------------------
__device__ __forceinline__ void ffma2(u64t& d, u64t a, u64t b) {
    asm("fma.rn.f32x2 %0, %1, %2, %0;" : "+l"(d) : "l"(a), "l"(b));
}
__device__ __forceinline__ u64t packdup(float x) {
    u64t r; asm("mov.b64 %0, {%1, %1};" : "=l"(r) : "f"(x)); return r;
}
__device__ __forceinline__ float2 unpack2(u64t v) {
    float2 f; asm("mov.b64 {%0, %1}, %2;" : "=f"(f.x), "=f"(f.y) : "l"(v)); return f;
}

// ------------------------------ barriers ------------------------------------
__device__ __forceinline__ unsigned ld_acq(unsigned* p) {
    unsigned v;
    asm volatile("ld.acquire.gpu.u32 %0, [%1];" : "=r"(v) : "l"(p) : "memory");
    return v;
}

__device__ __forceinline__ void barrier_sync(int idx, int n, unsigned& ep) {
    __syncthreads();
    if (threadIdx.x == 0) {
        ep += 1;
        __threadfence();
        unsigned prev = atomicAdd(&g_barCnt[idx], 1u);
        if (prev == (unsigned)(n - 1)) {
            atomicExch(&g_barCnt[idx], 0u);
            __threadfence();
            atomicExch(&g_barEp[idx], ep);
        } else {
            while (ld_acq(&g_barEp[idx]) < ep) { }
        }
        __threadfence();
    }
    __syncthreads();
}

// --------------------- 64x64 tile GEMM (C-strides = NP) ---------------------
// A: 64 rows, stride lda; B: K x 64 at Bm, stride NP; C: 64 x 64, stride NP.
// 256 threads, 4x4 microtile computed as 4x(2x f32x2), K multiple of 16.
__device__ __forceinline__ void tile_gemm64(
    const float* __restrict__ A, int lda,
    const float* __restrict__ Bm,
    float* __restrict__ C, int K, float* sh)
{
    float* hT = sh;            // [16][68]
    float* Us = sh + 16 * 68;  // [16][64]
    int tid  = threadIdx.x;
    int arow = tid >> 2, akq = (tid & 3) << 2;
    int brow = tid >> 4, bc  = (tid & 15) << 2;
    int ty   = tid >> 4, tx  = tid & 15;

    u64t acc2[4][2];
#pragma unroll
    for (int i = 0; i < 4; i++) { acc2[i][0] = 0ull; acc2[i][1] = 0ull; }

    const float* Aptr = A + arow * lda + akq;
    const float* Bptr = Bm + brow * NP + bc;
    float4 av = *(const float4*)Aptr;
    float4 bv = *(const float4*)Bptr;

    for (int k0 = 0; k0 < K; k0 += 16) {
        __syncthreads();
        hT[(akq + 0) * 68 + arow] = av.x;
        hT[(akq + 1) * 68 + arow] = av.y;
        hT[(akq + 2) * 68 + arow] = av.z;
        hT[(akq + 3) * 68 + arow] = av.w;
        *(float4*)(Us + (brow << 6) + bc) = bv;
        __syncthreads();
        if (k0 + 16 < K) {
            av = *(const float4*)(Aptr + k0 + 16);
            bv = *(const float4*)(Bptr + (size_t)(k0 + 16) * NP);
        }
#pragma unroll
        for (int kk = 0; kk < 16; kk++) {
            float4 a = *(float4*)(hT + kk * 68 + (ty << 2));
            const u64t* bp = (const u64t*)(Us + (kk << 6) + (tx << 2));
            u64t b0 = bp[0];
            u64t b1 = bp[1];
            u64t ad;
            ad = packdup(a.x); ffma2(acc2[0][0], ad, b0); ffma2(acc2[0][1], ad, b1);
            ad = packdup(a.y); ffma2(acc2[1][0], ad, b0); ffma2(acc2[1][1], ad, b1);
            ad = packdup(a.z); ffma2(acc2[2][0], ad, b0); ffma2(acc2[2][1], ad, b1);
            ad = packdup(a.w); ffma2(acc2[3][0], ad, b0); ffma2(acc2[3][1], ad, b1);
        }
    }
#pragma unroll
    for (int i = 0; i < 4; i++) {
        float2 lo = unpack2(acc2[i][0]);
        float2 hi = unpack2(acc2[i][1]);
        *(float4*)(C + (size_t)((ty << 2) + i) * NP + (tx << 2)) =
            make_float4(lo.x, lo.y, hi.x, hi.y);
    }
}

// ------------------------------ main kernel ---------------------------------
__global__ void __launch_bounds__(NTHR, 1) hrnn_kernel(
    const float* __restrict__ x, const int* __restrict__ mask,
    const float* __restrict__ W, const float* __restrict__ U,
    const float* __restrict__ bias, const float* __restrict__ gam,
    const float* __restrict__ bet, float* __restrict__ out)
{
    __shared__ float sh_gemm[16 * 68 + 16 * 64];
    __shared__ float sh_s[Nn];
    __shared__ float sh_red[16];
    __shared__ float sh_sc[8];

    int cta = blockIdx.x, tid = threadIdx.x;
    int gtid = cta * NTHR + tid;
    const int nthr = NCTA * NTHR;

    // ------------------------------- prep -----------------------------------
    for (int i = gtid; i < Tn * Bn * Dn; i += nthr) {
        int d = i & (Dn - 1);
        int row = i >> 10;
        int t = row >> 7, b = row & 127;
        g_X[i] = (d < In) ? x[(b * Tn + t) * In + d] : 0.f;
    }
    for (int i = gtid; i < Dn * NP; i += nthr) {
        int col = i % NP, r = i / NP;
        float wv = 0.f, uv = 0.f;
        if (col < Nn) { wv = W[r * Nn + col]; uv = U[r * Nn + col]; }
        g_Wp[i] = wv;
        g_Up[i] = uv;
    }
    for (int i = gtid; i < Tn * Bn; i += nthr) { g_fkseq[i] = 0.f; g_hvseq[i] = 1.f; }

    int g = cta / GCTA;      // group 0/1
    int c = cta % GCTA;      // CTA within group
    unsigned epG = 0, epL = 0;
    if (tid == 0) {
        epG = ld_acq(&g_barEp[2]);   // persistent-counter-safe base
        epL = ld_acq(&g_barEp[g]);
    }
    barrier_sync(2, NCTA, epG);

    const float* gam0 = gam;
    const float* gam1 = gam + Nn;
    const float* bet0 = bet;
    const float* bet1 = bet + Nn;
    const int b0g = g * GB;

    for (int lev = 0; lev < DEPTH; lev++) {
        // ---------------- xW GEMM: 128 t-tiles x 9 col strips ----------------
        for (int tau = c; tau < Tn * 9; tau += GCTA) {
            int t = tau / 9, j = tau - t * 9;
            tile_gemm64(&g_X[(size_t)(t * Bn + b0g) * Dn], Dn,
                        &g_Wp[j * 64],
                        &g_XWraw[(size_t)(t * Bn + b0g) * NP + j * 64],
                        Dn, sh_gemm);
        }
        barrier_sync(g, GCTA, epL);

        // ---------------- LN of xW rows -> spre; init carries ----------------
        for (int lr = c; lr < Tn * GB; lr += GCTA) {
            int t = lr >> 6, bl = lr & 63;
            const float* row = &g_XWraw[(size_t)(t * Bn + b0g + bl) * NP];
            float v0 = row[tid];
            float v1 = row[tid + 256];
            float v2 = (tid == 0) ? row[512] : 0.f;
            float s = v0 + v1 + v2;
            float q = v0 * v0 + v1 * v1 + v2 * v2;
#pragma unroll
            for (int o = 16; o > 0; o >>= 1) {
                s += __shfl_down_sync(0xffffffffu, s, o);
                q += __shfl_down_sync(0xffffffffu, q, o);
            }
            if ((tid & 31) == 0) { sh_red[tid >> 5] = s; sh_red[8 + (tid >> 5)] = q; }
            __syncthreads();
            if (tid == 0) {
                float S = 0.f, Q = 0.f;
#pragma unroll
                for (int w = 0; w < 8; w++) { S += sh_red[w]; Q += sh_red[8 + w]; }
                float mean = S * (1.f / (float)Nn);
                float var  = Q * (1.f / (float)Nn) - mean * mean;
                sh_sc[0] = mean;
                sh_sc[1] = 1.f / (sqrtf(var + EPSV) + EPSV);
            }
            __syncthreads();
            float mean = sh_sc[0], inv = sh_sc[1];
            float* o = &g_spre[(size_t)(t * Bn + b0g + bl) * NP];
            o[tid]       = gam0[tid] * ((v0 - mean) * inv) + bet0[tid] + bias[tid];
            o[tid + 256] = gam0[tid + 256] * ((v1 - mean) * inv) + bet0[tid + 256] + bias[tid + 256];
            if (tid == 0)
                o[512] = gam0[512] * ((v2 - mean) * inv) + bet0[512] + bias[512];
            __syncthreads();
        }
        for (int i = c * NTHR + tid; i < GB * Dn; i += GCTA * NTHR)
            g_h[b0g * Dn + i] = 0.f;
        for (int i = c * NTHR + tid; i < GB; i += GCTA * NTHR) {
            g_fk[b0g + i] = 0.f;
            g_hv[b0g + i] = 0.f;
        }
        barrier_sync(g, GCTA, epL);

        // ------------------------------ scan ---------------------------------
        for (int t = 0; t < Tn; t++) {
            // phase A: split-K h@U partials
            if (c < 72) {
                int j = c >> 3, ks = c & 7;
                tile_gemm64(&g_h[(size_t)b0g * Dn + ks * 128], Dn,
                            &g_Up[(size_t)(ks * 128) * NP + j * 64],
                            &g_Gpart[(size_t)((g * 8 + ks) * GB) * NP + j * 64],
                            128, sh_gemm);
            }
            barrier_sync(g, GCTA, epL);

            // phase B: one CTA per batch
            if (c < GB) {
                int b = b0g + c;
                float v0 = 0.f, v1 = 0.f, v2 = 0.f;
#pragma unroll
                for (int ks = 0; ks < 8; ks++) {
                    const float* gp = &g_Gpart[(size_t)((g * 8 + ks) * GB + c) * NP];
                    v0 += gp[tid];
                    v1 += gp[tid + 256];
                    if (tid == 0) v2 += gp[512];
                }
                float s = v0 + v1 + v2;
                float q = v0 * v0 + v1 * v1 + v2 * v2;
#pragma unroll
                for (int o = 16; o > 0; o >>= 1) {
                    s += __shfl_down_sync(0xffffffffu, s, o);
                    q += __shfl_down_sync(0xffffffffu, q, o);
                }
                if ((tid & 31) == 0) { sh_red[tid >> 5] = s; sh_red[8 + (tid >> 5)] = q; }
                __syncthreads();
                if (tid == 0) {
                    float S = 0.f, Q = 0.f;
#pragma unroll
                    for (int w = 0; w < 8; w++) { S += sh_red[w]; Q += sh_red[8 + w]; }
                    float mean = S * (1.f / (float)Nn);
                    float var  = Q * (1.f / (float)Nn) - mean * mean;
                    sh_sc[0] = mean;
                    sh_sc[1] = 1.f / (sqrtf(var + EPSV) + EPSV);
                }
                __syncthreads();
                float mean = sh_sc[0], inv = sh_sc[1];

                const float* sp = &g_spre[(size_t)(t * Bn + b) * NP];
                float sum2_0 = gam1[0] * ((v0 - mean) * inv) + bet1[0]; // tid 0 only
                float s0 = sp[tid]       + gam1[tid]       * ((v0 - mean) * inv) + bet1[tid];
                float s1 = sp[tid + 256] + gam1[tid + 256] * ((v1 - mean) * inv) + bet1[tid + 256];
                sh_s[tid]       = s0;
                sh_s[tid + 256] = s1;
                if (tid == 0)
                    sh_s[512] = sp[512] + gam1[512] * ((v2 - mean) * inv) + bet1[512];

                if (tid == 0) {
                    float fk_tm1  = g_fk[b];
                    float hv_tm1  = g_hv[b];
                    float fkp_tm1 = g_fkseq[t * Bn + b];
                    float fkp     = (t + 1 < Tn) ? g_fkseq[(t + 1) * Bn + b] : 0.f;
                    float hvp     = g_hvseq[t * Bn + b];
                    bool  mk      = mask[b * Tn + t] > 0;
                    bool  mkprev  = (t > 0) ? (mask[b * Tn + t - 1] > 0) : false;
                    bool  mk2     = (t > 0) && mkprev && !mk;

                    float fk_both = fminf(fmaxf(0.2f * s0 + 0.5f, 0.f), 1.f);
                    float fk_t1   = fminf(fmaxf(0.2f * (sum2_0 + bias[0]) + 0.5f, 0.f), 1.f);
                    float fk = fkp_tm1 + (1.f - fkp_tm1) *
                               (fk_tm1 * fk_both + (1.f - fk_tm1) * fk_t1);
                    if (mk2) fk = 0.f;

                    float h_only = hv_tm1 * fk * (fkp + (1.f - fkp) * (1.f - hvp));
                    float x_only = hvp * (1.f - fkp) * (1.f - fk + fk * (1.f - hv_tm1));
                    float both   = (1.f - fkp) * fk * hv_tm1 * hvp;
                    float hv = 1.f - (1.f - h_only) * (1.f - x_only) * (1.f - both);

                    float fk_out = mk ? fk : fk_tm1;
                    float hv_out = mk ? hv : hv_tm1;
                    if (mk2) fk_out = 0.f;

                    sh_sc[2] = h_only; sh_sc[3] = x_only;
                    sh_sc[4] = both;   sh_sc[5] = mk ? 1.f : 0.f;

                    g_fk[b] = fk_out;
                    g_hv[b] = hv_out;
                    g_fkseq[t * Bn + b] = fk_out;
                    g_hvseq[t * Bn + b] = hv_out;
                }
                __syncthreads();

                float h_only = sh_sc[2], x_only = sh_sc[3];
                float both = sh_sc[4], mkf = sh_sc[5];
#pragma unroll
                for (int e = 0; e < 4; e++) {
                    int d = tid + (e << 8);
                    float x_t   = g_X[(size_t)(t * Bn + b) * Dn + d];
                    float h_tm1 = g_h[(size_t)b * Dn + d];
                    float h_new = (d < In) ? 0.f : tanhf(sh_s[d - (In - 1)]);
                    float h = h_only * h_tm1 + x_only * x_t + both * h_new;
                    h = mkf * h + (1.f - mkf) * h_tm1;
                    g_h[(size_t)b * Dn + d] = h;
                    g_X[(size_t)(t * Bn + b) * Dn + d] = h;
                }
            }
            barrier_sync(g, GCTA, epL);
        }
    }

    // ------------------------------ output ----------------------------------
    for (int i = c * NTHR + tid; i < GB * Hn; i += GCTA * NTHR) {
        int bl = i >> 9, j = i & 511;
        out[(size_t)(b0g + bl) * Hn + j] = g_h[(size_t)(b0g + bl) * Dn + In + j];
    }
}

// ------------------------------- launcher -----------------------------------
extern "C" void kernel_launch(void* const* d_in, const int* in_sizes, int n_in,
                              void* d_out, int out_size) {
    const float* x      = (const float*)d_in[0];
    const int*   mask   = (const int*)d_in[1];
    const float* W      = (const float*)d_in[2];
    const float* U      = (const float*)d_in[3];
    const float* bias   = (const float*)d_in[4];
    const float* gammas = (const float*)d_in[5];
    const float* betas  = (const float*)d_in[6];
    float* out = (float*)d_out;

    hrnn_kernel<<<NCTA, NTHR>>>(x, mask, W, U, bias, gammas, betas, out);
}